// round 9
// baseline (speedup 1.0000x reference)
#include <cuda_runtime.h>
#include <cuda_bf16.h>

typedef unsigned long long ull_t;
typedef unsigned int uint32;

#define D      64
#define H      128
#define GDIM   64
#define NMAX   100000
#define PQ_STRIDE 132
#define EWARPS 12
#define ETHREADS 384

// ---------- packed fp32x2 helpers (pre-kernels) ----------
static __device__ __forceinline__ ull_t ffma2(ull_t a, ull_t b, ull_t c) {
    ull_t d;
    asm("fma.rn.f32x2 %0, %1, %2, %3;" : "=l"(d) : "l"(a), "l"(b), "l"(c));
    return d;
}
static __device__ __forceinline__ ull_t fadd2(ull_t a, ull_t b) {
    ull_t d;
    asm("add.rn.f32x2 %0, %1, %2;" : "=l"(d) : "l"(a), "l"(b));
    return d;
}
static __device__ __forceinline__ ull_t pack2(float lo, float hi) {
    ull_t r;
    asm("mov.b64 %0, {%1, %2};" : "=l"(r) : "f"(lo), "f"(hi));
    return r;
}
static __device__ __forceinline__ void unpack2(ull_t v, float& lo, float& hi) {
    asm("mov.b64 {%0, %1}, %2;" : "=f"(lo), "=f"(hi) : "l"(v));
}

// ---------- device scratch ----------
__device__ float g_P[(size_t)NMAX * H];   // x @ W1[64:128]  (receiver)
__device__ float g_Q[(size_t)NMAX * H];   // x @ W1[128:192] + R[batch[n]] (b1 folded)
__device__ float g_R[GDIM * H];           // u @ W1[192:256] + b1

// ---------- bf16 split/pack ----------
static __device__ __forceinline__ uint32 bpack(__nv_bfloat16 x, __nv_bfloat16 y) {
    __nv_bfloat162 t = __halves2bfloat162(x, y);
    return *reinterpret_cast<uint32*>(&t);
}
static __device__ __forceinline__ void splitpack(float x, float y,
                                                 uint32& hi, uint32& lo) {
    __nv_bfloat16 xh = __float2bfloat16_rn(x);
    __nv_bfloat16 yh = __float2bfloat16_rn(y);
    hi = bpack(xh, yh);
    __nv_bfloat16 xl = __float2bfloat16_rn(x - __bfloat162float(xh));
    __nv_bfloat16 yl = __float2bfloat16_rn(y - __bfloat162float(yh));
    lo = bpack(xl, yl);
}

// mma.sync m16n8k16 bf16, fp32 acc
static __device__ __forceinline__ void mma4(float* d, const uint32* a,
                                            uint32 b0, uint32 b1) {
    asm("mma.sync.aligned.m16n8k16.row.col.f32.bf16.bf16.f32 "
        "{%0,%1,%2,%3}, {%4,%5,%6,%7}, {%8,%9}, {%0,%1,%2,%3};"
        : "+f"(d[0]), "+f"(d[1]), "+f"(d[2]), "+f"(d[3])
        : "r"(a[0]), "r"(a[1]), "r"(a[2]), "r"(a[3]), "r"(b0), "r"(b1));
}

// ================= R = u @ W1_glob + b1 =================
__global__ void k_preR(const float* __restrict__ u,
                       const float* __restrict__ W1,
                       const float* __restrict__ b1) {
    __shared__ float us[D];
    int g = blockIdx.x;
    int j = threadIdx.x;
    if (j < D) us[j] = u[g * D + j];
    __syncthreads();
    float acc = b1[j];
#pragma unroll 8
    for (int k = 0; k < D; k++)
        acc += us[k] * W1[(192 + k) * H + j];
    g_R[g * H + j] = acc;
}

// ================= P, Q' node projections =================
__global__ void k_prePQ(const float* __restrict__ x,
                        const float* __restrict__ W1,
                        const int* __restrict__ batch,
                        int N) {
    __shared__ __align__(16) float xs[8][D];
    int t = threadIdx.x;
    int base = blockIdx.x * 8;
    {
        int nn = base + (t >> 4);
        int part = t & 15;
        if (nn >= N) nn = N - 1;
        ((float4*)&xs[0][0])[t] = ((const float4*)x)[(size_t)nn * 16 + part];
    }
    __syncthreads();

    int  jp  = t & 63;
    bool isQ = (t >= 64);
    const float* W = W1 + (isQ ? 128 : 64) * H + 2 * jp;

    ull_t acc[8];
#pragma unroll
    for (int m = 0; m < 8; m++) acc[m] = pack2(0.0f, 0.0f);

#pragma unroll 4
    for (int k = 0; k < D; k += 2) {
        ull_t w0 = *(const ull_t*)(W + (size_t)k * H);
        ull_t w1 = *(const ull_t*)(W + (size_t)(k + 1) * H);
#pragma unroll
        for (int m = 0; m < 8; m++) {
            ull_t xv = *(const ull_t*)&xs[m][k];
            float x0, x1;
            unpack2(xv, x0, x1);
            acc[m] = ffma2(pack2(x0, x0), w0, acc[m]);
            acc[m] = ffma2(pack2(x1, x1), w1, acc[m]);
        }
    }

    float* dst = isQ ? g_Q : g_P;
#pragma unroll
    for (int m = 0; m < 8; m++) {
        int n = base + m;
        if (n >= N) break;
        ull_t v = acc[m];
        if (isQ) {
            int bg = batch[n];
            v = fadd2(v, *(const ull_t*)(g_R + bg * H + 2 * jp));
        }
        *(ull_t*)(dst + (size_t)n * H + 2 * jp) = v;
    }
}

// ========== edge kernel: mma.sync, 12 warps/SM, pipelined, lean epilogue ======
__global__ __launch_bounds__(ETHREADS, 1) void k_edge_mma(
    const float* __restrict__ e,
    const float* __restrict__ W1,
    const float* __restrict__ W2,
    const float* __restrict__ b2,
    const float* __restrict__ ln_g,
    const float* __restrict__ ln_b,
    const int* __restrict__ eidx,
    float* __restrict__ out,
    int E) {
    extern __shared__ __align__(16) char smem_raw[];
    uint4* sB1 = (uint4*)smem_raw;                    // [4][16][32] W1 frags hi+lo
    uint4* sB2 = sB1 + 4 * 16 * 32;                   // [8][16][32] W2 frags hi+lo
    float* sb2 = (float*)(sB2 + 8 * 16 * 32);         // [128]
    float* slg = sb2 + 128;                           // [128]
    float* slb = slg + 128;                           // [128]
    float* spq = slb + 128;                           // [EWARPS][16*PQ_STRIDE]

    int tid = threadIdx.x;

    // ---- prepack B fragments ----
    for (int idx = tid; idx < 4 * 16 * 32; idx += ETHREADS) {
        int lane = idx & 31, nf = (idx >> 5) & 15, kf = idx >> 9;
        int n  = nf * 8 + (lane >> 2);
        int k0 = kf * 16 + (lane & 3) * 2;
        float w00 = W1[(size_t)(k0    ) * H + n];
        float w01 = W1[(size_t)(k0 + 1) * H + n];
        float w10 = W1[(size_t)(k0 + 8) * H + n];
        float w11 = W1[(size_t)(k0 + 9) * H + n];
        uint32 b0h, b0l, b1h, b1l;
        splitpack(w00, w01, b0h, b0l);
        splitpack(w10, w11, b1h, b1l);
        sB1[idx] = make_uint4(b0h, b1h, b0l, b1l);
    }
    for (int idx = tid; idx < 8 * 16 * 32; idx += ETHREADS) {
        int lane = idx & 31, nf = (idx >> 5) & 15, kf = idx >> 9;
        int n  = nf * 8 + (lane >> 2);
        int k0 = kf * 16 + (lane & 3) * 2;
        float w00 = W2[(size_t)(k0    ) * H + n];
        float w01 = W2[(size_t)(k0 + 1) * H + n];
        float w10 = W2[(size_t)(k0 + 8) * H + n];
        float w11 = W2[(size_t)(k0 + 9) * H + n];
        uint32 b0h, b0l, b1h, b1l;
        splitpack(w00, w01, b0h, b0l);
        splitpack(w10, w11, b1h, b1l);
        sB2[idx] = make_uint4(b0h, b1h, b0l, b1l);
    }
    for (int i = tid; i < 128; i += ETHREADS) {
        sb2[i] = b2[i]; slg[i] = ln_g[i]; slb[i] = ln_b[i];
    }
    __syncthreads();

    int lane = tid & 31;
    int warp = tid >> 5;
    int g = lane >> 2;        // mma row group 0..7
    int c = lane & 3;         // mma col group 0..3
    int m = lane >> 1;        // staging slot 0..15
    int h = lane & 1;         // staging half

    float* wsd = spq + warp * (16 * PQ_STRIDE);

    int ngroups = (E + 15) >> 4;
    int grp = blockIdx.x * EWARPS + warp;
    int nwarps = gridDim.x * EWARPS;

    // ---- prologue: prefetch indices + raw e rows for first group ----
    int rowm = 0, colm = 0;
    float2 ev0[8], ev1[8];
    if (grp < ngroups) {
        int i0 = grp << 4;
        int em = min(i0 + m, E - 1);
        rowm = eidx[em];
        colm = eidx[(size_t)E + em];
        int e0i = min(i0 + g, E - 1);
        int e1i = min(i0 + g + 8, E - 1);
        const float* er0 = e + (size_t)e0i * D;
        const float* er1 = e + (size_t)e1i * D;
#pragma unroll
        for (int kf = 0; kf < 4; kf++) {
            ev0[2 * kf]     = *(const float2*)(er0 + kf * 16 + 2 * c);
            ev0[2 * kf + 1] = *(const float2*)(er0 + kf * 16 + 2 * c + 8);
            ev1[2 * kf]     = *(const float2*)(er1 + kf * 16 + 2 * c);
            ev1[2 * kf + 1] = *(const float2*)(er1 + kf * 16 + 2 * c + 8);
        }
    }

    while (grp < ngroups) {
        int i0 = grp << 4;
        __syncwarp();   // prev iteration's pq reads done before restage

        // ---- stage pq = P[col] + Q[row] into smem (hidden by GEMM1) ----
        {
            const float4* Pr = (const float4*)(g_P + (size_t)colm * H + h * 64);
            const float4* Qr = (const float4*)(g_Q + (size_t)rowm * H + h * 64);
            float4* dst = (float4*)(wsd + m * PQ_STRIDE + h * 64);
#pragma unroll
            for (int i = 0; i < 16; i++) {
                float4 a = Pr[i], b = Qr[i];
                dst[i] = make_float4(a.x + b.x, a.y + b.y, a.z + b.z, a.w + b.w);
            }
        }

        // ---- splitpack A frags from prefetched regs ----
        uint32 aH[4][4], aL[4][4];
#pragma unroll
        for (int kf = 0; kf < 4; kf++) {
            splitpack(ev0[2 * kf].x,     ev0[2 * kf].y,     aH[kf][0], aL[kf][0]);
            splitpack(ev1[2 * kf].x,     ev1[2 * kf].y,     aH[kf][1], aL[kf][1]);
            splitpack(ev0[2 * kf + 1].x, ev0[2 * kf + 1].y, aH[kf][2], aL[kf][2]);
            splitpack(ev1[2 * kf + 1].x, ev1[2 * kf + 1].y, aH[kf][3], aL[kf][3]);
        }

        // ---- GEMM1: acc = e @ W1[0:64]  (3-term) ----
        float acc[16][4];
#pragma unroll
        for (int nf = 0; nf < 16; nf++) {
            acc[nf][0] = 0.f; acc[nf][1] = 0.f;
            acc[nf][2] = 0.f; acc[nf][3] = 0.f;
        }
#pragma unroll
        for (int kf = 0; kf < 4; kf++) {
#pragma unroll
            for (int nf = 0; nf < 16; nf++) {
                uint4 B = sB1[(kf * 16 + nf) * 32 + lane];
                mma4(acc[nf], aH[kf], B.x, B.y);   // hi*hi
                mma4(acc[nf], aH[kf], B.z, B.w);   // hi*lo
                mma4(acc[nf], aL[kf], B.x, B.y);   // lo*hi
            }
        }
        __syncwarp();   // staging visible before pq reads below

        // ---- prefetch next group's indices + e rows ----
        int ngrp = grp + nwarps;
        if (ngrp < ngroups) {
            int ni0 = ngrp << 4;
            int em = min(ni0 + m, E - 1);
            rowm = eidx[em];
            colm = eidx[(size_t)E + em];
            int e0i = min(ni0 + g, E - 1);
            int e1i = min(ni0 + g + 8, E - 1);
            const float* er0 = e + (size_t)e0i * D;
            const float* er1 = e + (size_t)e1i * D;
#pragma unroll
            for (int kf = 0; kf < 4; kf++) {
                ev0[2 * kf]     = *(const float2*)(er0 + kf * 16 + 2 * c);
                ev0[2 * kf + 1] = *(const float2*)(er0 + kf * 16 + 2 * c + 8);
                ev1[2 * kf]     = *(const float2*)(er1 + kf * 16 + 2 * c);
                ev1[2 * kf + 1] = *(const float2*)(er1 + kf * 16 + 2 * c + 8);
            }
        }

        // ---- +pq (smem), relu, D->A conversion ----
        uint32 A2h[8][4], A2l[8][4];
#pragma unroll
        for (int kf = 0; kf < 8; kf++) {
            int na = 2 * kf, nb = 2 * kf + 1;
            float2 p0a = *(const float2*)(wsd + g * PQ_STRIDE + na * 8 + 2 * c);
            float2 p0b = *(const float2*)(wsd + g * PQ_STRIDE + nb * 8 + 2 * c);
            float2 p1a = *(const float2*)(wsd + (g + 8) * PQ_STRIDE + na * 8 + 2 * c);
            float2 p1b = *(const float2*)(wsd + (g + 8) * PQ_STRIDE + nb * 8 + 2 * c);
            float a0 = fmaxf(acc[na][0] + p0a.x, 0.f);
            float a1 = fmaxf(acc[na][1] + p0a.y, 0.f);
            float a2 = fmaxf(acc[nb][0] + p0b.x, 0.f);
            float a3 = fmaxf(acc[nb][1] + p0b.y, 0.f);
            float b0 = fmaxf(acc[na][2] + p1a.x, 0.f);
            float b1v = fmaxf(acc[na][3] + p1a.y, 0.f);
            float b2v = fmaxf(acc[nb][2] + p1b.x, 0.f);
            float b3 = fmaxf(acc[nb][3] + p1b.y, 0.f);
            splitpack(a0, a1,  A2h[kf][0], A2l[kf][0]);   // row g,   k-lo
            splitpack(b0, b1v, A2h[kf][1], A2l[kf][1]);   // row g+8, k-lo
            splitpack(a2, a3,  A2h[kf][2], A2l[kf][2]);   // row g,   k-hi
            splitpack(b2v, b3, A2h[kf][3], A2l[kf][3]);   // row g+8, k-hi
        }

        float acc2[16][4];
#pragma unroll
        for (int nf = 0; nf < 16; nf++) {
            acc2[nf][0] = 0.f; acc2[nf][1] = 0.f;
            acc2[nf][2] = 0.f; acc2[nf][3] = 0.f;
        }

        // ---- GEMM2: acc2 = relu(h1) @ W2  (3-term) ----
#pragma unroll
        for (int kf = 0; kf < 8; kf++) {
#pragma unroll
            for (int nf = 0; nf < 16; nf++) {
                uint4 B = sB2[(kf * 16 + nf) * 32 + lane];
                mma4(acc2[nf], A2h[kf], B.x, B.y);
                mma4(acc2[nf], A2h[kf], B.z, B.w);
                mma4(acc2[nf], A2l[kf], B.x, B.y);
            }
        }

        // ---- +b2, relu, LayerNorm stats ----
        float s0 = 0.f, ss0 = 0.f, s8 = 0.f, ss8 = 0.f;
#pragma unroll
        for (int nf = 0; nf < 16; nf++) {
            float2 bb = *(const float2*)(sb2 + nf * 8 + 2 * c);
            float v0 = fmaxf(acc2[nf][0] + bb.x, 0.f);
            float v1 = fmaxf(acc2[nf][1] + bb.y, 0.f);
            float v2 = fmaxf(acc2[nf][2] + bb.x, 0.f);
            float v3 = fmaxf(acc2[nf][3] + bb.y, 0.f);
            acc2[nf][0] = v0; acc2[nf][1] = v1;
            acc2[nf][2] = v2; acc2[nf][3] = v3;
            s0 += v0 + v1;  ss0 += v0 * v0 + v1 * v1;
            s8 += v2 + v3;  ss8 += v2 * v2 + v3 * v3;
        }
        s0  += __shfl_xor_sync(0xffffffffu, s0, 1);
        s0  += __shfl_xor_sync(0xffffffffu, s0, 2);
        ss0 += __shfl_xor_sync(0xffffffffu, ss0, 1);
        ss0 += __shfl_xor_sync(0xffffffffu, ss0, 2);
        s8  += __shfl_xor_sync(0xffffffffu, s8, 1);
        s8  += __shfl_xor_sync(0xffffffffu, s8, 2);
        ss8 += __shfl_xor_sync(0xffffffffu, ss8, 1);
        ss8 += __shfl_xor_sync(0xffffffffu, ss8, 2);

        float m0 = s0 * (1.0f / H);
        float r0f = rsqrtf(ss0 * (1.0f / H) - m0 * m0 + 1e-5f);
        float m8 = s8 * (1.0f / H);
        float r8f = rsqrtf(ss8 * (1.0f / H) - m8 * m8 + 1e-5f);

        int eg  = i0 + g;
        int eg8 = i0 + g + 8;
        bool w0ok = eg < E, w8ok = eg8 < E;
        float* o0 = out + (size_t)eg  * H + 2 * c;
        float* o8 = out + (size_t)eg8 * H + 2 * c;
        // lean epilogue: y = fma(v, rg, cb) with rg = r*g, cb = b - m*rg
#pragma unroll
        for (int nf = 0; nf < 16; nf++) {
            float2 gg = *(const float2*)(slg + nf * 8 + 2 * c);
            float2 be = *(const float2*)(slb + nf * 8 + 2 * c);
            if (w0ok) {
                float rgx = r0f * gg.x, rgy = r0f * gg.y;
                float cbx = fmaf(-m0, rgx, be.x);
                float cby = fmaf(-m0, rgy, be.y);
                *(float2*)(o0 + nf * 8) =
                    make_float2(fmaf(acc2[nf][0], rgx, cbx),
                                fmaf(acc2[nf][1], rgy, cby));
            }
            if (w8ok) {
                float rgx = r8f * gg.x, rgy = r8f * gg.y;
                float cbx = fmaf(-m8, rgx, be.x);
                float cby = fmaf(-m8, rgy, be.y);
                *(float2*)(o8 + nf * 8) =
                    make_float2(fmaf(acc2[nf][2], rgx, cbx),
                                fmaf(acc2[nf][3], rgy, cby));
            }
        }

        grp = ngrp;
    }
}

// ================= launch =================
extern "C" void kernel_launch(void* const* d_in, const int* in_sizes, int n_in,
                              void* d_out, int out_size) {
    const float* x     = (const float*)d_in[0];
    const float* e     = (const float*)d_in[1];
    const float* u     = (const float*)d_in[2];
    const float* W1    = (const float*)d_in[3];
    const float* b1    = (const float*)d_in[4];
    const float* W2    = (const float*)d_in[5];
    const float* b2    = (const float*)d_in[6];
    const float* ln_g  = (const float*)d_in[7];
    const float* ln_b  = (const float*)d_in[8];
    const int*   eidx  = (const int*)d_in[9];
    const int*   batch = (const int*)d_in[10];
    float*       out   = (float*)d_out;

    int N = in_sizes[0] / D;   // 100000
    int E = in_sizes[1] / D;   // 1000000

    // smem: B1 32KB + B2 64KB + consts 1.5KB + pq staging 12*8.25KB
    const int SMEM = (4 * 16 * 32 + 8 * 16 * 32) * 16 + 3 * 128 * 4
                   + EWARPS * 16 * PQ_STRIDE * 4;   // 201216 B
    cudaFuncSetAttribute(k_edge_mma, cudaFuncAttributeMaxDynamicSharedMemorySize, SMEM);

    k_preR<<<GDIM, H>>>(u, W1, b1);
    k_prePQ<<<(N + 7) / 8, 128>>>(x, W1, batch, N);
    k_edge_mma<<<152, ETHREADS, SMEM>>>(e, W1, W2, b2, ln_g, ln_b, eidx, out, E);
}

// round 10
// speedup vs baseline: 1.0484x; 1.0484x over previous
#include <cuda_runtime.h>
#include <cuda_bf16.h>

typedef unsigned long long ull_t;
typedef unsigned int uint32;

#define D      64
#define H      128
#define GDIM   64
#define NMAX   100000
#define PQ_STRIDE 132
#define EWARPS 9
#define ETHREADS 288

// ---------- packed fp32x2 helpers (pre-kernels) ----------
static __device__ __forceinline__ ull_t ffma2(ull_t a, ull_t b, ull_t c) {
    ull_t d;
    asm("fma.rn.f32x2 %0, %1, %2, %3;" : "=l"(d) : "l"(a), "l"(b), "l"(c));
    return d;
}
static __device__ __forceinline__ ull_t fadd2(ull_t a, ull_t b) {
    ull_t d;
    asm("add.rn.f32x2 %0, %1, %2;" : "=l"(d) : "l"(a), "l"(b));
    return d;
}
static __device__ __forceinline__ ull_t pack2(float lo, float hi) {
    ull_t r;
    asm("mov.b64 %0, {%1, %2};" : "=l"(r) : "f"(lo), "f"(hi));
    return r;
}
static __device__ __forceinline__ void unpack2(ull_t v, float& lo, float& hi) {
    asm("mov.b64 {%0, %1}, %2;" : "=f"(lo), "=f"(hi) : "l"(v));
}

// ---------- device scratch ----------
__device__ float g_P[(size_t)NMAX * H];   // x @ W1[64:128]  (receiver)
__device__ float g_Q[(size_t)NMAX * H];   // x @ W1[128:192] + R[batch[n]] (b1 folded)
__device__ float g_R[GDIM * H];           // u @ W1[192:256] + b1

// ---------- bf16 split/pack ----------
static __device__ __forceinline__ uint32 bpack(__nv_bfloat16 x, __nv_bfloat16 y) {
    __nv_bfloat162 t = __halves2bfloat162(x, y);
    return *reinterpret_cast<uint32*>(&t);
}
static __device__ __forceinline__ void splitpack(float x, float y,
                                                 uint32& hi, uint32& lo) {
    __nv_bfloat16 xh = __float2bfloat16_rn(x);
    __nv_bfloat16 yh = __float2bfloat16_rn(y);
    hi = bpack(xh, yh);
    __nv_bfloat16 xl = __float2bfloat16_rn(x - __bfloat162float(xh));
    __nv_bfloat16 yl = __float2bfloat16_rn(y - __bfloat162float(yh));
    lo = bpack(xl, yl);
}

// mma.sync m16n8k16 bf16, fp32 acc
static __device__ __forceinline__ void mma4(float* d, const uint32* a,
                                            uint32 b0, uint32 b1) {
    asm("mma.sync.aligned.m16n8k16.row.col.f32.bf16.bf16.f32 "
        "{%0,%1,%2,%3}, {%4,%5,%6,%7}, {%8,%9}, {%0,%1,%2,%3};"
        : "+f"(d[0]), "+f"(d[1]), "+f"(d[2]), "+f"(d[3])
        : "r"(a[0]), "r"(a[1]), "r"(a[2]), "r"(a[3]), "r"(b0), "r"(b1));
}

// ================= R = u @ W1_glob + b1 =================
__global__ void k_preR(const float* __restrict__ u,
                       const float* __restrict__ W1,
                       const float* __restrict__ b1) {
    __shared__ float us[D];
    int g = blockIdx.x;
    int j = threadIdx.x;
    if (j < D) us[j] = u[g * D + j];
    __syncthreads();
    float acc = b1[j];
#pragma unroll 8
    for (int k = 0; k < D; k++)
        acc += us[k] * W1[(192 + k) * H + j];
    g_R[g * H + j] = acc;
}

// ================= P, Q' node projections =================
__global__ void k_prePQ(const float* __restrict__ x,
                        const float* __restrict__ W1,
                        const int* __restrict__ batch,
                        int N) {
    __shared__ __align__(16) float xs[8][D];
    int t = threadIdx.x;
    int base = blockIdx.x * 8;
    {
        int nn = base + (t >> 4);
        int part = t & 15;
        if (nn >= N) nn = N - 1;
        ((float4*)&xs[0][0])[t] = ((const float4*)x)[(size_t)nn * 16 + part];
    }
    __syncthreads();

    int  jp  = t & 63;
    bool isQ = (t >= 64);
    const float* W = W1 + (isQ ? 128 : 64) * H + 2 * jp;

    ull_t acc[8];
#pragma unroll
    for (int m = 0; m < 8; m++) acc[m] = pack2(0.0f, 0.0f);

#pragma unroll 4
    for (int k = 0; k < D; k += 2) {
        ull_t w0 = *(const ull_t*)(W + (size_t)k * H);
        ull_t w1 = *(const ull_t*)(W + (size_t)(k + 1) * H);
#pragma unroll
        for (int m = 0; m < 8; m++) {
            ull_t xv = *(const ull_t*)&xs[m][k];
            float x0, x1;
            unpack2(xv, x0, x1);
            acc[m] = ffma2(pack2(x0, x0), w0, acc[m]);
            acc[m] = ffma2(pack2(x1, x1), w1, acc[m]);
        }
    }

    float* dst = isQ ? g_Q : g_P;
#pragma unroll
    for (int m = 0; m < 8; m++) {
        int n = base + m;
        if (n >= N) break;
        ull_t v = acc[m];
        if (isQ) {
            int bg = batch[n];
            v = fadd2(v, *(const ull_t*)(g_R + bg * H + 2 * jp));
        }
        *(ull_t*)(dst + (size_t)n * H + 2 * jp) = v;
    }
}

// ========== edge kernel: mma.sync, 9 warps/SM (no spill), pipelined ==========
__global__ __launch_bounds__(ETHREADS, 1) void k_edge_mma(
    const float* __restrict__ e,
    const float* __restrict__ W1,
    const float* __restrict__ W2,
    const float* __restrict__ b2,
    const float* __restrict__ ln_g,
    const float* __restrict__ ln_b,
    const int* __restrict__ eidx,
    float* __restrict__ out,
    int E) {
    extern __shared__ __align__(16) char smem_raw[];
    uint4* sB1 = (uint4*)smem_raw;                    // [4][16][32] W1 frags hi+lo
    uint4* sB2 = sB1 + 4 * 16 * 32;                   // [8][16][32] W2 frags hi+lo
    float* sb2 = (float*)(sB2 + 8 * 16 * 32);         // [128]
    float* slg = sb2 + 128;                           // [128]
    float* slb = slg + 128;                           // [128]
    float* spq = slb + 128;                           // [EWARPS][16*PQ_STRIDE]

    int tid = threadIdx.x;

    // ---- prepack B fragments ----
    for (int idx = tid; idx < 4 * 16 * 32; idx += ETHREADS) {
        int lane = idx & 31, nf = (idx >> 5) & 15, kf = idx >> 9;
        int n  = nf * 8 + (lane >> 2);
        int k0 = kf * 16 + (lane & 3) * 2;
        float w00 = W1[(size_t)(k0    ) * H + n];
        float w01 = W1[(size_t)(k0 + 1) * H + n];
        float w10 = W1[(size_t)(k0 + 8) * H + n];
        float w11 = W1[(size_t)(k0 + 9) * H + n];
        uint32 b0h, b0l, b1h, b1l;
        splitpack(w00, w01, b0h, b0l);
        splitpack(w10, w11, b1h, b1l);
        sB1[idx] = make_uint4(b0h, b1h, b0l, b1l);
    }
    for (int idx = tid; idx < 8 * 16 * 32; idx += ETHREADS) {
        int lane = idx & 31, nf = (idx >> 5) & 15, kf = idx >> 9;
        int n  = nf * 8 + (lane >> 2);
        int k0 = kf * 16 + (lane & 3) * 2;
        float w00 = W2[(size_t)(k0    ) * H + n];
        float w01 = W2[(size_t)(k0 + 1) * H + n];
        float w10 = W2[(size_t)(k0 + 8) * H + n];
        float w11 = W2[(size_t)(k0 + 9) * H + n];
        uint32 b0h, b0l, b1h, b1l;
        splitpack(w00, w01, b0h, b0l);
        splitpack(w10, w11, b1h, b1l);
        sB2[idx] = make_uint4(b0h, b1h, b0l, b1l);
    }
    for (int i = tid; i < 128; i += ETHREADS) {
        sb2[i] = b2[i]; slg[i] = ln_g[i]; slb[i] = ln_b[i];
    }
    __syncthreads();

    int lane = tid & 31;
    int warp = tid >> 5;
    int g = lane >> 2;        // mma row group 0..7
    int c = lane & 3;         // mma col group 0..3
    int m = lane >> 1;        // staging slot 0..15
    int h = lane & 1;         // staging half

    float* wsd = spq + warp * (16 * PQ_STRIDE);

    int ngroups = (E + 15) >> 4;
    int grp = blockIdx.x * EWARPS + warp;
    int nwarps = gridDim.x * EWARPS;

    // ---- prologue: prefetch indices + raw e rows for first group ----
    int rowm = 0, colm = 0;
    float2 ev0[8], ev1[8];
    if (grp < ngroups) {
        int i0 = grp << 4;
        int em = min(i0 + m, E - 1);
        rowm = eidx[em];
        colm = eidx[(size_t)E + em];
        int e0i = min(i0 + g, E - 1);
        int e1i = min(i0 + g + 8, E - 1);
        const float* er0 = e + (size_t)e0i * D;
        const float* er1 = e + (size_t)e1i * D;
#pragma unroll
        for (int kf = 0; kf < 4; kf++) {
            ev0[2 * kf]     = *(const float2*)(er0 + kf * 16 + 2 * c);
            ev0[2 * kf + 1] = *(const float2*)(er0 + kf * 16 + 2 * c + 8);
            ev1[2 * kf]     = *(const float2*)(er1 + kf * 16 + 2 * c);
            ev1[2 * kf + 1] = *(const float2*)(er1 + kf * 16 + 2 * c + 8);
        }
    }

    while (grp < ngroups) {
        int i0 = grp << 4;
        __syncwarp();   // prev iteration's pq reads done before restage

        // ---- stage pq = P[col] + Q[row] into smem (hidden by GEMM1) ----
        {
            const float4* Pr = (const float4*)(g_P + (size_t)colm * H + h * 64);
            const float4* Qr = (const float4*)(g_Q + (size_t)rowm * H + h * 64);
            float4* dst = (float4*)(wsd + m * PQ_STRIDE + h * 64);
#pragma unroll
            for (int i = 0; i < 16; i++) {
                float4 a = Pr[i], b = Qr[i];
                dst[i] = make_float4(a.x + b.x, a.y + b.y, a.z + b.z, a.w + b.w);
            }
        }

        // ---- splitpack A frags from prefetched regs ----
        uint32 aH[4][4], aL[4][4];
#pragma unroll
        for (int kf = 0; kf < 4; kf++) {
            splitpack(ev0[2 * kf].x,     ev0[2 * kf].y,     aH[kf][0], aL[kf][0]);
            splitpack(ev1[2 * kf].x,     ev1[2 * kf].y,     aH[kf][1], aL[kf][1]);
            splitpack(ev0[2 * kf + 1].x, ev0[2 * kf + 1].y, aH[kf][2], aL[kf][2]);
            splitpack(ev1[2 * kf + 1].x, ev1[2 * kf + 1].y, aH[kf][3], aL[kf][3]);
        }

        // ---- GEMM1: acc = e @ W1[0:64]  (3-term) ----
        float acc[16][4];
#pragma unroll
        for (int nf = 0; nf < 16; nf++) {
            acc[nf][0] = 0.f; acc[nf][1] = 0.f;
            acc[nf][2] = 0.f; acc[nf][3] = 0.f;
        }
#pragma unroll
        for (int kf = 0; kf < 4; kf++) {
#pragma unroll
            for (int nf = 0; nf < 16; nf++) {
                uint4 B = sB1[(kf * 16 + nf) * 32 + lane];
                mma4(acc[nf], aH[kf], B.x, B.y);   // hi*hi
                mma4(acc[nf], aH[kf], B.z, B.w);   // hi*lo
                mma4(acc[nf], aL[kf], B.x, B.y);   // lo*hi
            }
        }
        __syncwarp();   // staging visible before pq reads below

        // ---- prefetch next group's indices + e rows ----
        int ngrp = grp + nwarps;
        if (ngrp < ngroups) {
            int ni0 = ngrp << 4;
            int em = min(ni0 + m, E - 1);
            rowm = eidx[em];
            colm = eidx[(size_t)E + em];
            int e0i = min(ni0 + g, E - 1);
            int e1i = min(ni0 + g + 8, E - 1);
            const float* er0 = e + (size_t)e0i * D;
            const float* er1 = e + (size_t)e1i * D;
#pragma unroll
            for (int kf = 0; kf < 4; kf++) {
                ev0[2 * kf]     = *(const float2*)(er0 + kf * 16 + 2 * c);
                ev0[2 * kf + 1] = *(const float2*)(er0 + kf * 16 + 2 * c + 8);
                ev1[2 * kf]     = *(const float2*)(er1 + kf * 16 + 2 * c);
                ev1[2 * kf + 1] = *(const float2*)(er1 + kf * 16 + 2 * c + 8);
            }
        }

        // ---- +pq (smem), relu, D->A conversion ----
        uint32 A2h[8][4], A2l[8][4];
#pragma unroll
        for (int kf = 0; kf < 8; kf++) {
            int na = 2 * kf, nb = 2 * kf + 1;
            float2 p0a = *(const float2*)(wsd + g * PQ_STRIDE + na * 8 + 2 * c);
            float2 p0b = *(const float2*)(wsd + g * PQ_STRIDE + nb * 8 + 2 * c);
            float2 p1a = *(const float2*)(wsd + (g + 8) * PQ_STRIDE + na * 8 + 2 * c);
            float2 p1b = *(const float2*)(wsd + (g + 8) * PQ_STRIDE + nb * 8 + 2 * c);
            float a0 = fmaxf(acc[na][0] + p0a.x, 0.f);
            float a1 = fmaxf(acc[na][1] + p0a.y, 0.f);
            float a2 = fmaxf(acc[nb][0] + p0b.x, 0.f);
            float a3 = fmaxf(acc[nb][1] + p0b.y, 0.f);
            float b0 = fmaxf(acc[na][2] + p1a.x, 0.f);
            float b1v = fmaxf(acc[na][3] + p1a.y, 0.f);
            float b2v = fmaxf(acc[nb][2] + p1b.x, 0.f);
            float b3 = fmaxf(acc[nb][3] + p1b.y, 0.f);
            splitpack(a0, a1,  A2h[kf][0], A2l[kf][0]);   // row g,   k-lo
            splitpack(b0, b1v, A2h[kf][1], A2l[kf][1]);   // row g+8, k-lo
            splitpack(a2, a3,  A2h[kf][2], A2l[kf][2]);   // row g,   k-hi
            splitpack(b2v, b3, A2h[kf][3], A2l[kf][3]);   // row g+8, k-hi
        }

        // ---- GEMM2: acc2 = b2 + relu(h1) @ W2  (3-term; b2 folded in init) ----
        float acc2[16][4];
#pragma unroll
        for (int nf = 0; nf < 16; nf++) {
            float2 bb = *(const float2*)(sb2 + nf * 8 + 2 * c);
            acc2[nf][0] = bb.x; acc2[nf][1] = bb.y;
            acc2[nf][2] = bb.x; acc2[nf][3] = bb.y;
        }
#pragma unroll
        for (int kf = 0; kf < 8; kf++) {
#pragma unroll
            for (int nf = 0; nf < 16; nf++) {
                uint4 B = sB2[(kf * 16 + nf) * 32 + lane];
                mma4(acc2[nf], A2h[kf], B.x, B.y);
                mma4(acc2[nf], A2h[kf], B.z, B.w);
                mma4(acc2[nf], A2l[kf], B.x, B.y);
            }
        }

        // ---- relu, LayerNorm stats ----
        float s0 = 0.f, ss0 = 0.f, s8 = 0.f, ss8 = 0.f;
#pragma unroll
        for (int nf = 0; nf < 16; nf++) {
            float v0 = fmaxf(acc2[nf][0], 0.f);
            float v1 = fmaxf(acc2[nf][1], 0.f);
            float v2 = fmaxf(acc2[nf][2], 0.f);
            float v3 = fmaxf(acc2[nf][3], 0.f);
            acc2[nf][0] = v0; acc2[nf][1] = v1;
            acc2[nf][2] = v2; acc2[nf][3] = v3;
            s0 += v0 + v1;  ss0 += v0 * v0 + v1 * v1;
            s8 += v2 + v3;  ss8 += v2 * v2 + v3 * v3;
        }
        s0  += __shfl_xor_sync(0xffffffffu, s0, 1);
        s0  += __shfl_xor_sync(0xffffffffu, s0, 2);
        ss0 += __shfl_xor_sync(0xffffffffu, ss0, 1);
        ss0 += __shfl_xor_sync(0xffffffffu, ss0, 2);
        s8  += __shfl_xor_sync(0xffffffffu, s8, 1);
        s8  += __shfl_xor_sync(0xffffffffu, s8, 2);
        ss8 += __shfl_xor_sync(0xffffffffu, ss8, 1);
        ss8 += __shfl_xor_sync(0xffffffffu, ss8, 2);

        float m0 = s0 * (1.0f / H);
        float r0f = rsqrtf(ss0 * (1.0f / H) - m0 * m0 + 1e-5f);
        float m8 = s8 * (1.0f / H);
        float r8f = rsqrtf(ss8 * (1.0f / H) - m8 * m8 + 1e-5f);

        int eg  = i0 + g;
        int eg8 = i0 + g + 8;
        bool w0ok = eg < E, w8ok = eg8 < E;
        float* o0 = out + (size_t)eg  * H + 2 * c;
        float* o8 = out + (size_t)eg8 * H + 2 * c;
        // lean epilogue: y = fma(v, rg, cb) with rg = r*g, cb = b - m*rg
#pragma unroll
        for (int nf = 0; nf < 16; nf++) {
            float2 gg = *(const float2*)(slg + nf * 8 + 2 * c);
            float2 be = *(const float2*)(slb + nf * 8 + 2 * c);
            if (w0ok) {
                float rgx = r0f * gg.x, rgy = r0f * gg.y;
                float cbx = fmaf(-m0, rgx, be.x);
                float cby = fmaf(-m0, rgy, be.y);
                *(float2*)(o0 + nf * 8) =
                    make_float2(fmaf(acc2[nf][0], rgx, cbx),
                                fmaf(acc2[nf][1], rgy, cby));
            }
            if (w8ok) {
                float rgx = r8f * gg.x, rgy = r8f * gg.y;
                float cbx = fmaf(-m8, rgx, be.x);
                float cby = fmaf(-m8, rgy, be.y);
                *(float2*)(o8 + nf * 8) =
                    make_float2(fmaf(acc2[nf][2], rgx, cbx),
                                fmaf(acc2[nf][3], rgy, cby));
            }
        }

        grp = ngrp;
    }
}

// ================= launch =================
extern "C" void kernel_launch(void* const* d_in, const int* in_sizes, int n_in,
                              void* d_out, int out_size) {
    const float* x     = (const float*)d_in[0];
    const float* e     = (const float*)d_in[1];
    const float* u     = (const float*)d_in[2];
    const float* W1    = (const float*)d_in[3];
    const float* b1    = (const float*)d_in[4];
    const float* W2    = (const float*)d_in[5];
    const float* b2    = (const float*)d_in[6];
    const float* ln_g  = (const float*)d_in[7];
    const float* ln_b  = (const float*)d_in[8];
    const int*   eidx  = (const int*)d_in[9];
    const int*   batch = (const int*)d_in[10];
    float*       out   = (float*)d_out;

    int N = in_sizes[0] / D;   // 100000
    int E = in_sizes[1] / D;   // 1000000

    // smem: B1 32KB + B2 64KB + consts 1.5KB + pq staging 9*8.25KB
    const int SMEM = (4 * 16 * 32 + 8 * 16 * 32) * 16 + 3 * 128 * 4
                   + EWARPS * 16 * PQ_STRIDE * 4;   // 175104 B
    cudaFuncSetAttribute(k_edge_mma, cudaFuncAttributeMaxDynamicSharedMemorySize, SMEM);

    k_preR<<<GDIM, H>>>(u, W1, b1);
    k_prePQ<<<(N + 7) / 8, 128>>>(x, W1, batch, N);
    k_edge_mma<<<152, ETHREADS, SMEM>>>(e, W1, W2, b2, ln_g, ln_b, eidx, out, E);
}

// round 11
// speedup vs baseline: 1.3849x; 1.3211x over previous
#include <cuda_runtime.h>
#include <cuda_fp16.h>

typedef unsigned long long ull_t;
typedef unsigned int uint32;

#define D      64
#define H      128
#define GDIM   64
#define NMAX   100000
#define PQ_STRIDE 132
#define EWARPS 8
#define ETHREADS 256

// ---------- packed fp32x2 helpers (pre-kernels) ----------
static __device__ __forceinline__ ull_t ffma2(ull_t a, ull_t b, ull_t c) {
    ull_t d;
    asm("fma.rn.f32x2 %0, %1, %2, %3;" : "=l"(d) : "l"(a), "l"(b), "l"(c));
    return d;
}
static __device__ __forceinline__ ull_t fadd2(ull_t a, ull_t b) {
    ull_t d;
    asm("add.rn.f32x2 %0, %1, %2;" : "=l"(d) : "l"(a), "l"(b));
    return d;
}
static __device__ __forceinline__ ull_t pack2(float lo, float hi) {
    ull_t r;
    asm("mov.b64 %0, {%1, %2};" : "=l"(r) : "f"(lo), "f"(hi));
    return r;
}
static __device__ __forceinline__ void unpack2(ull_t v, float& lo, float& hi) {
    asm("mov.b64 {%0, %1}, %2;" : "=f"(lo), "=f"(hi) : "l"(v));
}

// ---------- device scratch ----------
__device__ float g_P[(size_t)NMAX * H];   // x @ W1[64:128]  (receiver)
__device__ float g_Q[(size_t)NMAX * H];   // x @ W1[128:192] + R[batch[n]] (b1 folded)
__device__ float g_R[GDIM * H];           // u @ W1[192:256] + b1

// ---------- fp16 pack/split ----------
static __device__ __forceinline__ uint32 hpack(__half x, __half y) {
    __half2 t = __halves2half2(x, y);
    return *reinterpret_cast<uint32*>(&t);
}
// single-rounded fp16 pair (for B / weights)
static __device__ __forceinline__ uint32 hround(float x, float y) {
    return hpack(__float2half_rn(x), __float2half_rn(y));
}
// 2-term split of A: hi = fp16(x), lo = fp16(x - hi)
static __device__ __forceinline__ void hsplit(float x, float y,
                                              uint32& hi, uint32& lo) {
    __half xh = __float2half_rn(x);
    __half yh = __float2half_rn(y);
    hi = hpack(xh, yh);
    __half xl = __float2half_rn(x - __half2float(xh));
    __half yl = __float2half_rn(y - __half2float(yh));
    lo = hpack(xl, yl);
}

// mma.sync m16n8k16 fp16 inputs, fp32 acc
static __device__ __forceinline__ void mma4(float* d, const uint32* a,
                                            uint32 b0, uint32 b1) {
    asm("mma.sync.aligned.m16n8k16.row.col.f32.f16.f16.f32 "
        "{%0,%1,%2,%3}, {%4,%5,%6,%7}, {%8,%9}, {%0,%1,%2,%3};"
        : "+f"(d[0]), "+f"(d[1]), "+f"(d[2]), "+f"(d[3])
        : "r"(a[0]), "r"(a[1]), "r"(a[2]), "r"(a[3]), "r"(b0), "r"(b1));
}

// ================= R = u @ W1_glob + b1 =================
__global__ void k_preR(const float* __restrict__ u,
                       const float* __restrict__ W1,
                       const float* __restrict__ b1) {
    __shared__ float us[D];
    int g = blockIdx.x;
    int j = threadIdx.x;
    if (j < D) us[j] = u[g * D + j];
    __syncthreads();
    float acc = b1[j];
#pragma unroll 8
    for (int k = 0; k < D; k++)
        acc += us[k] * W1[(192 + k) * H + j];
    g_R[g * H + j] = acc;
}

// ================= P, Q' node projections =================
__global__ void k_prePQ(const float* __restrict__ x,
                        const float* __restrict__ W1,
                        const int* __restrict__ batch,
                        int N) {
    __shared__ __align__(16) float xs[8][D];
    int t = threadIdx.x;
    int base = blockIdx.x * 8;
    {
        int nn = base + (t >> 4);
        int part = t & 15;
        if (nn >= N) nn = N - 1;
        ((float4*)&xs[0][0])[t] = ((const float4*)x)[(size_t)nn * 16 + part];
    }
    __syncthreads();

    int  jp  = t & 63;
    bool isQ = (t >= 64);
    const float* W = W1 + (isQ ? 128 : 64) * H + 2 * jp;

    ull_t acc[8];
#pragma unroll
    for (int m = 0; m < 8; m++) acc[m] = pack2(0.0f, 0.0f);

#pragma unroll 4
    for (int k = 0; k < D; k += 2) {
        ull_t w0 = *(const ull_t*)(W + (size_t)k * H);
        ull_t w1 = *(const ull_t*)(W + (size_t)(k + 1) * H);
#pragma unroll
        for (int m = 0; m < 8; m++) {
            ull_t xv = *(const ull_t*)&xs[m][k];
            float x0, x1;
            unpack2(xv, x0, x1);
            acc[m] = ffma2(pack2(x0, x0), w0, acc[m]);
            acc[m] = ffma2(pack2(x1, x1), w1, acc[m]);
        }
    }

    float* dst = isQ ? g_Q : g_P;
#pragma unroll
    for (int m = 0; m < 8; m++) {
        int n = base + m;
        if (n >= N) break;
        ull_t v = acc[m];
        if (isQ) {
            int bg = batch[n];
            v = fadd2(v, *(const ull_t*)(g_R + bg * H + 2 * jp));
        }
        *(ull_t*)(dst + (size_t)n * H + 2 * jp) = v;
    }
}

// ===== edge kernel: fp16 2-term mma.sync, 8 warps, pipelined, lean epilogue ====
__global__ __launch_bounds__(ETHREADS, 1) void k_edge_mma(
    const float* __restrict__ e,
    const float* __restrict__ W1,
    const float* __restrict__ W2,
    const float* __restrict__ b2,
    const float* __restrict__ ln_g,
    const float* __restrict__ ln_b,
    const int* __restrict__ eidx,
    float* __restrict__ out,
    int E) {
    extern __shared__ __align__(16) char smem_raw[];
    uint2* sB1 = (uint2*)smem_raw;                    // [4][16][32] W1 frags (fp16)
    uint2* sB2 = sB1 + 4 * 16 * 32;                   // [8][16][32] W2 frags (fp16)
    float* sb2 = (float*)(sB2 + 8 * 16 * 32);         // [128]
    float* slg = sb2 + 128;                           // [128]
    float* slb = slg + 128;                           // [128]
    float* spq = slb + 128;                           // [EWARPS][16*PQ_STRIDE]

    int tid = threadIdx.x;

    // ---- prepack B fragments (single-rounded fp16) ----
    for (int idx = tid; idx < 4 * 16 * 32; idx += ETHREADS) {
        int lane = idx & 31, nf = (idx >> 5) & 15, kf = idx >> 9;
        int n  = nf * 8 + (lane >> 2);
        int k0 = kf * 16 + (lane & 3) * 2;
        uint32 b0 = hround(W1[(size_t)(k0    ) * H + n], W1[(size_t)(k0 + 1) * H + n]);
        uint32 b1 = hround(W1[(size_t)(k0 + 8) * H + n], W1[(size_t)(k0 + 9) * H + n]);
        sB1[idx] = make_uint2(b0, b1);
    }
    for (int idx = tid; idx < 8 * 16 * 32; idx += ETHREADS) {
        int lane = idx & 31, nf = (idx >> 5) & 15, kf = idx >> 9;
        int n  = nf * 8 + (lane >> 2);
        int k0 = kf * 16 + (lane & 3) * 2;
        uint32 b0 = hround(W2[(size_t)(k0    ) * H + n], W2[(size_t)(k0 + 1) * H + n]);
        uint32 b1 = hround(W2[(size_t)(k0 + 8) * H + n], W2[(size_t)(k0 + 9) * H + n]);
        sB2[idx] = make_uint2(b0, b1);
    }
    for (int i = tid; i < 128; i += ETHREADS) {
        sb2[i] = b2[i]; slg[i] = ln_g[i]; slb[i] = ln_b[i];
    }
    __syncthreads();

    int lane = tid & 31;
    int warp = tid >> 5;
    int g = lane >> 2;        // mma row group 0..7
    int c = lane & 3;         // mma col group 0..3
    int m = lane >> 1;        // staging slot 0..15
    int h = lane & 1;         // staging half

    float* wsd = spq + warp * (16 * PQ_STRIDE);

    int ngroups = (E + 15) >> 4;
    int grp = blockIdx.x * EWARPS + warp;
    int nwarps = gridDim.x * EWARPS;

    // ---- prologue: prefetch indices + raw e rows for first group ----
    int rowm = 0, colm = 0;
    float2 ev0[8], ev1[8];
    if (grp < ngroups) {
        int i0 = grp << 4;
        int em = min(i0 + m, E - 1);
        rowm = eidx[em];
        colm = eidx[(size_t)E + em];
        int e0i = min(i0 + g, E - 1);
        int e1i = min(i0 + g + 8, E - 1);
        const float* er0 = e + (size_t)e0i * D;
        const float* er1 = e + (size_t)e1i * D;
#pragma unroll
        for (int kf = 0; kf < 4; kf++) {
            ev0[2 * kf]     = *(const float2*)(er0 + kf * 16 + 2 * c);
            ev0[2 * kf + 1] = *(const float2*)(er0 + kf * 16 + 2 * c + 8);
            ev1[2 * kf]     = *(const float2*)(er1 + kf * 16 + 2 * c);
            ev1[2 * kf + 1] = *(const float2*)(er1 + kf * 16 + 2 * c + 8);
        }
    }

    while (grp < ngroups) {
        int i0 = grp << 4;
        __syncwarp();   // prev iteration's pq reads done before restage

        // ---- stage pq = P[col] + Q[row] into smem (hidden by GEMM1) ----
        {
            const float4* Pr = (const float4*)(g_P + (size_t)colm * H + h * 64);
            const float4* Qr = (const float4*)(g_Q + (size_t)rowm * H + h * 64);
            float4* dst = (float4*)(wsd + m * PQ_STRIDE + h * 64);
#pragma unroll
            for (int i = 0; i < 16; i++) {
                float4 a = Pr[i], b = Qr[i];
                dst[i] = make_float4(a.x + b.x, a.y + b.y, a.z + b.z, a.w + b.w);
            }
        }

        // ---- split A frags (fp16 2-term) from prefetched regs ----
        uint32 aH[4][4], aL[4][4];
#pragma unroll
        for (int kf = 0; kf < 4; kf++) {
            hsplit(ev0[2 * kf].x,     ev0[2 * kf].y,     aH[kf][0], aL[kf][0]);
            hsplit(ev1[2 * kf].x,     ev1[2 * kf].y,     aH[kf][1], aL[kf][1]);
            hsplit(ev0[2 * kf + 1].x, ev0[2 * kf + 1].y, aH[kf][2], aL[kf][2]);
            hsplit(ev1[2 * kf + 1].x, ev1[2 * kf + 1].y, aH[kf][3], aL[kf][3]);
        }

        // ---- GEMM1: acc = e @ W1[0:64]  (2-term) ----
        float acc[16][4];
#pragma unroll
        for (int nf = 0; nf < 16; nf++) {
            acc[nf][0] = 0.f; acc[nf][1] = 0.f;
            acc[nf][2] = 0.f; acc[nf][3] = 0.f;
        }
#pragma unroll
        for (int kf = 0; kf < 4; kf++) {
#pragma unroll
            for (int nf = 0; nf < 16; nf++) {
                uint2 B = sB1[(kf * 16 + nf) * 32 + lane];
                mma4(acc[nf], aH[kf], B.x, B.y);   // hi*B
                mma4(acc[nf], aL[kf], B.x, B.y);   // lo*B
            }
        }
        __syncwarp();   // staging visible before pq reads below

        // ---- prefetch next group's indices + e rows ----
        int ngrp = grp + nwarps;
        if (ngrp < ngroups) {
            int ni0 = ngrp << 4;
            int em = min(ni0 + m, E - 1);
            rowm = eidx[em];
            colm = eidx[(size_t)E + em];
            int e0i = min(ni0 + g, E - 1);
            int e1i = min(ni0 + g + 8, E - 1);
            const float* er0 = e + (size_t)e0i * D;
            const float* er1 = e + (size_t)e1i * D;
#pragma unroll
            for (int kf = 0; kf < 4; kf++) {
                ev0[2 * kf]     = *(const float2*)(er0 + kf * 16 + 2 * c);
                ev0[2 * kf + 1] = *(const float2*)(er0 + kf * 16 + 2 * c + 8);
                ev1[2 * kf]     = *(const float2*)(er1 + kf * 16 + 2 * c);
                ev1[2 * kf + 1] = *(const float2*)(er1 + kf * 16 + 2 * c + 8);
            }
        }

        // ---- +pq (smem), relu, D->A conversion (fp16 2-term) ----
        // A-frag order: [0]=row g k-lo, [1]=row g+8 k-lo, [2]=row g k-hi, [3]=row g+8 k-hi
        uint32 A2h[8][4], A2l[8][4];
#pragma unroll
        for (int kf = 0; kf < 8; kf++) {
            int na = 2 * kf, nb = 2 * kf + 1;
            float2 p0a = *(const float2*)(wsd + g * PQ_STRIDE + na * 8 + 2 * c);
            float2 p0b = *(const float2*)(wsd + g * PQ_STRIDE + nb * 8 + 2 * c);
            float2 p1a = *(const float2*)(wsd + (g + 8) * PQ_STRIDE + na * 8 + 2 * c);
            float2 p1b = *(const float2*)(wsd + (g + 8) * PQ_STRIDE + nb * 8 + 2 * c);
            float a0 = fmaxf(acc[na][0] + p0a.x, 0.f);
            float a1 = fmaxf(acc[na][1] + p0a.y, 0.f);
            float a2 = fmaxf(acc[nb][0] + p0b.x, 0.f);
            float a3 = fmaxf(acc[nb][1] + p0b.y, 0.f);
            float b0 = fmaxf(acc[na][2] + p1a.x, 0.f);
            float b1v = fmaxf(acc[na][3] + p1a.y, 0.f);
            float b2v = fmaxf(acc[nb][2] + p1b.x, 0.f);
            float b3 = fmaxf(acc[nb][3] + p1b.y, 0.f);
            hsplit(a0, a1,  A2h[kf][0], A2l[kf][0]);   // row g,   k-lo
            hsplit(b0, b1v, A2h[kf][1], A2l[kf][1]);   // row g+8, k-lo
            hsplit(a2, a3,  A2h[kf][2], A2l[kf][2]);   // row g,   k-hi
            hsplit(b2v, b3, A2h[kf][3], A2l[kf][3]);   // row g+8, k-hi
        }

        // ---- GEMM2: acc2 = b2 + relu(h1) @ W2  (2-term; b2 folded in init) ----
        float acc2[16][4];
#pragma unroll
        for (int nf = 0; nf < 16; nf++) {
            float2 bb = *(const float2*)(sb2 + nf * 8 + 2 * c);
            acc2[nf][0] = bb.x; acc2[nf][1] = bb.y;
            acc2[nf][2] = bb.x; acc2[nf][3] = bb.y;
        }
#pragma unroll
        for (int kf = 0; kf < 8; kf++) {
#pragma unroll
            for (int nf = 0; nf < 16; nf++) {
                uint2 B = sB2[(kf * 16 + nf) * 32 + lane];
                mma4(acc2[nf], A2h[kf], B.x, B.y);
                mma4(acc2[nf], A2l[kf], B.x, B.y);
            }
        }

        // ---- relu, LayerNorm stats ----
        float s0 = 0.f, ss0 = 0.f, s8 = 0.f, ss8 = 0.f;
#pragma unroll
        for (int nf = 0; nf < 16; nf++) {
            float v0 = fmaxf(acc2[nf][0], 0.f);
            float v1 = fmaxf(acc2[nf][1], 0.f);
            float v2 = fmaxf(acc2[nf][2], 0.f);
            float v3 = fmaxf(acc2[nf][3], 0.f);
            acc2[nf][0] = v0; acc2[nf][1] = v1;
            acc2[nf][2] = v2; acc2[nf][3] = v3;
            s0 += v0 + v1;  ss0 += v0 * v0 + v1 * v1;
            s8 += v2 + v3;  ss8 += v2 * v2 + v3 * v3;
        }
        s0  += __shfl_xor_sync(0xffffffffu, s0, 1);
        s0  += __shfl_xor_sync(0xffffffffu, s0, 2);
        ss0 += __shfl_xor_sync(0xffffffffu, ss0, 1);
        ss0 += __shfl_xor_sync(0xffffffffu, ss0, 2);
        s8  += __shfl_xor_sync(0xffffffffu, s8, 1);
        s8  += __shfl_xor_sync(0xffffffffu, s8, 2);
        ss8 += __shfl_xor_sync(0xffffffffu, ss8, 1);
        ss8 += __shfl_xor_sync(0xffffffffu, ss8, 2);

        float m0 = s0 * (1.0f / H);
        float r0f = rsqrtf(ss0 * (1.0f / H) - m0 * m0 + 1e-5f);
        float m8 = s8 * (1.0f / H);
        float r8f = rsqrtf(ss8 * (1.0f / H) - m8 * m8 + 1e-5f);

        int eg  = i0 + g;
        int eg8 = i0 + g + 8;
        bool w0ok = eg < E, w8ok = eg8 < E;
        float* o0 = out + (size_t)eg  * H + 2 * c;
        float* o8 = out + (size_t)eg8 * H + 2 * c;
        // lean epilogue: y = fma(v, rg, cb) with rg = r*g, cb = b - m*rg
#pragma unroll
        for (int nf = 0; nf < 16; nf++) {
            float2 gg = *(const float2*)(slg + nf * 8 + 2 * c);
            float2 be = *(const float2*)(slb + nf * 8 + 2 * c);
            if (w0ok) {
                float rgx = r0f * gg.x, rgy = r0f * gg.y;
                float cbx = fmaf(-m0, rgx, be.x);
                float cby = fmaf(-m0, rgy, be.y);
                *(float2*)(o0 + nf * 8) =
                    make_float2(fmaf(acc2[nf][0], rgx, cbx),
                                fmaf(acc2[nf][1], rgy, cby));
            }
            if (w8ok) {
                float rgx = r8f * gg.x, rgy = r8f * gg.y;
                float cbx = fmaf(-m8, rgx, be.x);
                float cby = fmaf(-m8, rgy, be.y);
                *(float2*)(o8 + nf * 8) =
                    make_float2(fmaf(acc2[nf][2], rgx, cbx),
                                fmaf(acc2[nf][3], rgy, cby));
            }
        }

        grp = ngrp;
    }
}

// ================= launch =================
extern "C" void kernel_launch(void* const* d_in, const int* in_sizes, int n_in,
                              void* d_out, int out_size) {
    const float* x     = (const float*)d_in[0];
    const float* e     = (const float*)d_in[1];
    const float* u     = (const float*)d_in[2];
    const float* W1    = (const float*)d_in[3];
    const float* b1    = (const float*)d_in[4];
    const float* W2    = (const float*)d_in[5];
    const float* b2    = (const float*)d_in[6];
    const float* ln_g  = (const float*)d_in[7];
    const float* ln_b  = (const float*)d_in[8];
    const int*   eidx  = (const int*)d_in[9];
    const int*   batch = (const int*)d_in[10];
    float*       out   = (float*)d_out;

    int N = in_sizes[0] / D;   // 100000
    int E = in_sizes[1] / D;   // 1000000

    // smem: B1 16KB + B2 32KB + consts 1.5KB + pq staging 8*8.25KB
    const int SMEM = (4 * 16 * 32 + 8 * 16 * 32) * 8 + 3 * 128 * 4
                   + EWARPS * 16 * PQ_STRIDE * 4;   // 118272 B
    cudaFuncSetAttribute(k_edge_mma, cudaFuncAttributeMaxDynamicSharedMemorySize, SMEM);

    k_preR<<<GDIM, H>>>(u, W1, b1);
    k_prePQ<<<(N + 7) / 8, 128>>>(x, W1, batch, N);
    k_edge_mma<<<152, ETHREADS, SMEM>>>(e, W1, W2, b2, ln_g, ln_b, eidx, out, E);
}

// round 12
// speedup vs baseline: 1.3874x; 1.0018x over previous
#include <cuda_runtime.h>
#include <cuda_fp16.h>

typedef unsigned long long ull_t;
typedef unsigned int uint32;

#define D      64
#define H      128
#define GDIM   64
#define NMAX   100000
#define PQ_STRIDE 132
#define EWARPS 8
#define ETHREADS 256

// ---------- packed fp32x2 helpers (pre-kernels) ----------
static __device__ __forceinline__ ull_t ffma2(ull_t a, ull_t b, ull_t c) {
    ull_t d;
    asm("fma.rn.f32x2 %0, %1, %2, %3;" : "=l"(d) : "l"(a), "l"(b), "l"(c));
    return d;
}
static __device__ __forceinline__ ull_t fadd2(ull_t a, ull_t b) {
    ull_t d;
    asm("add.rn.f32x2 %0, %1, %2;" : "=l"(d) : "l"(a), "l"(b));
    return d;
}
static __device__ __forceinline__ ull_t pack2(float lo, float hi) {
    ull_t r;
    asm("mov.b64 %0, {%1, %2};" : "=l"(r) : "f"(lo), "f"(hi));
    return r;
}
static __device__ __forceinline__ void unpack2(ull_t v, float& lo, float& hi) {
    asm("mov.b64 {%0, %1}, %2;" : "=f"(lo), "=f"(hi) : "l"(v));
}

// ---------- device scratch ----------
__device__ float g_P[(size_t)NMAX * H];   // x @ W1[64:128]  (receiver)
__device__ float g_Q[(size_t)NMAX * H];   // x @ W1[128:192] + R[batch[n]] (b1 folded)
__device__ float g_R[GDIM * H];           // u @ W1[192:256] + b1

// ---------- fp16 pack/split ----------
static __device__ __forceinline__ uint32 hpack(__half x, __half y) {
    __half2 t = __halves2half2(x, y);
    return *reinterpret_cast<uint32*>(&t);
}
static __device__ __forceinline__ uint32 hround(float x, float y) {
    return hpack(__float2half_rn(x), __float2half_rn(y));
}
// 2-term split of A: hi = fp16(x), lo = fp16(x - hi)
static __device__ __forceinline__ void hsplit(float x, float y,
                                              uint32& hi, uint32& lo) {
    __half xh = __float2half_rn(x);
    __half yh = __float2half_rn(y);
    hi = hpack(xh, yh);
    __half xl = __float2half_rn(x - __half2float(xh));
    __half yl = __float2half_rn(y - __half2float(yh));
    lo = hpack(xl, yl);
}

// mma.sync m16n8k16 fp16 inputs, fp32 acc
static __device__ __forceinline__ void mma4(float* d, const uint32* a,
                                            uint32 b0, uint32 b1) {
    asm("mma.sync.aligned.m16n8k16.row.col.f32.f16.f16.f32 "
        "{%0,%1,%2,%3}, {%4,%5,%6,%7}, {%8,%9}, {%0,%1,%2,%3};"
        : "+f"(d[0]), "+f"(d[1]), "+f"(d[2]), "+f"(d[3])
        : "r"(a[0]), "r"(a[1]), "r"(a[2]), "r"(a[3]), "r"(b0), "r"(b1));
}

// ================= R = u @ W1_glob + b1 =================
__global__ void k_preR(const float* __restrict__ u,
                       const float* __restrict__ W1,
                       const float* __restrict__ b1) {
    __shared__ float us[D];
    int g = blockIdx.x;
    int j = threadIdx.x;
    if (j < D) us[j] = u[g * D + j];
    __syncthreads();
    float acc = b1[j];
#pragma unroll 8
    for (int k = 0; k < D; k++)
        acc += us[k] * W1[(192 + k) * H + j];
    g_R[g * H + j] = acc;
}

// ================= P, Q' node projections =================
__global__ void k_prePQ(const float* __restrict__ x,
                        const float* __restrict__ W1,
                        const int* __restrict__ batch,
                        int N) {
    __shared__ __align__(16) float xs[8][D];
    int t = threadIdx.x;
    int base = blockIdx.x * 8;
    {
        int nn = base + (t >> 4);
        int part = t & 15;
        if (nn >= N) nn = N - 1;
        ((float4*)&xs[0][0])[t] = ((const float4*)x)[(size_t)nn * 16 + part];
    }
    __syncthreads();

    int  jp  = t & 63;
    bool isQ = (t >= 64);
    const float* W = W1 + (isQ ? 128 : 64) * H + 2 * jp;

    ull_t acc[8];
#pragma unroll
    for (int m = 0; m < 8; m++) acc[m] = pack2(0.0f, 0.0f);

#pragma unroll 4
    for (int k = 0; k < D; k += 2) {
        ull_t w0 = *(const ull_t*)(W + (size_t)k * H);
        ull_t w1 = *(const ull_t*)(W + (size_t)(k + 1) * H);
#pragma unroll
        for (int m = 0; m < 8; m++) {
            ull_t xv = *(const ull_t*)&xs[m][k];
            float x0, x1;
            unpack2(xv, x0, x1);
            acc[m] = ffma2(pack2(x0, x0), w0, acc[m]);
            acc[m] = ffma2(pack2(x1, x1), w1, acc[m]);
        }
    }

    float* dst = isQ ? g_Q : g_P;
#pragma unroll
    for (int m = 0; m < 8; m++) {
        int n = base + m;
        if (n >= N) break;
        ull_t v = acc[m];
        if (isQ) {
            int bg = batch[n];
            v = fadd2(v, *(const ull_t*)(g_R + bg * H + 2 * jp));
        }
        *(ull_t*)(dst + (size_t)n * H + 2 * jp) = v;
    }
}

// == edge kernel: fp16 mma.sync (2-term GEMM1, 1-term GEMM2), 8 warps, pipelined ==
__global__ __launch_bounds__(ETHREADS, 1) void k_edge_mma(
    const float* __restrict__ e,
    const float* __restrict__ W1,
    const float* __restrict__ W2,
    const float* __restrict__ b2,
    const float* __restrict__ ln_g,
    const float* __restrict__ ln_b,
    const int* __restrict__ eidx,
    float* __restrict__ out,
    int E) {
    extern __shared__ __align__(16) char smem_raw[];
    uint2* sB1 = (uint2*)smem_raw;                    // [4][16][32] W1 frags (fp16)
    uint2* sB2 = sB1 + 4 * 16 * 32;                   // [8][16][32] W2 frags (fp16)
    float* sb2 = (float*)(sB2 + 8 * 16 * 32);         // [128]
    float* slg = sb2 + 128;                           // [128]
    float* slb = slg + 128;                           // [128]
    float* spq = slb + 128;                           // [EWARPS][16*PQ_STRIDE]

    int tid = threadIdx.x;

    // ---- prepack B fragments (single-rounded fp16) ----
    for (int idx = tid; idx < 4 * 16 * 32; idx += ETHREADS) {
        int lane = idx & 31, nf = (idx >> 5) & 15, kf = idx >> 9;
        int n  = nf * 8 + (lane >> 2);
        int k0 = kf * 16 + (lane & 3) * 2;
        uint32 b0 = hround(W1[(size_t)(k0    ) * H + n], W1[(size_t)(k0 + 1) * H + n]);
        uint32 b1 = hround(W1[(size_t)(k0 + 8) * H + n], W1[(size_t)(k0 + 9) * H + n]);
        sB1[idx] = make_uint2(b0, b1);
    }
    for (int idx = tid; idx < 8 * 16 * 32; idx += ETHREADS) {
        int lane = idx & 31, nf = (idx >> 5) & 15, kf = idx >> 9;
        int n  = nf * 8 + (lane >> 2);
        int k0 = kf * 16 + (lane & 3) * 2;
        uint32 b0 = hround(W2[(size_t)(k0    ) * H + n], W2[(size_t)(k0 + 1) * H + n]);
        uint32 b1 = hround(W2[(size_t)(k0 + 8) * H + n], W2[(size_t)(k0 + 9) * H + n]);
        sB2[idx] = make_uint2(b0, b1);
    }
    for (int i = tid; i < 128; i += ETHREADS) {
        sb2[i] = b2[i]; slg[i] = ln_g[i]; slb[i] = ln_b[i];
    }
    __syncthreads();

    int lane = tid & 31;
    int warp = tid >> 5;
    int g = lane >> 2;        // mma row group 0..7
    int c = lane & 3;         // mma col group 0..3
    int m = lane >> 1;        // staging slot 0..15
    int h = lane & 1;         // staging half

    float* wsd = spq + warp * (16 * PQ_STRIDE);

    int ngroups = (E + 15) >> 4;
    int grp = blockIdx.x * EWARPS + warp;
    int nwarps = gridDim.x * EWARPS;

    // ---- prologue: prefetch indices + raw e rows for first group ----
    int rowm = 0, colm = 0;
    float2 ev0[8], ev1[8];
    if (grp < ngroups) {
        int i0 = grp << 4;
        int em = min(i0 + m, E - 1);
        rowm = eidx[em];
        colm = eidx[(size_t)E + em];
        int e0i = min(i0 + g, E - 1);
        int e1i = min(i0 + g + 8, E - 1);
        const float* er0 = e + (size_t)e0i * D;
        const float* er1 = e + (size_t)e1i * D;
#pragma unroll
        for (int kf = 0; kf < 4; kf++) {
            ev0[2 * kf]     = *(const float2*)(er0 + kf * 16 + 2 * c);
            ev0[2 * kf + 1] = *(const float2*)(er0 + kf * 16 + 2 * c + 8);
            ev1[2 * kf]     = *(const float2*)(er1 + kf * 16 + 2 * c);
            ev1[2 * kf + 1] = *(const float2*)(er1 + kf * 16 + 2 * c + 8);
        }
    }

    while (grp < ngroups) {
        int i0 = grp << 4;
        __syncwarp();   // prev iteration's pq reads done before restage

        // ---- stage pq = P[col] + Q[row] into smem (hidden by GEMM1) ----
        {
            const float4* Pr = (const float4*)(g_P + (size_t)colm * H + h * 64);
            const float4* Qr = (const float4*)(g_Q + (size_t)rowm * H + h * 64);
            float4* dst = (float4*)(wsd + m * PQ_STRIDE + h * 64);
#pragma unroll
            for (int i = 0; i < 16; i++) {
                float4 a = Pr[i], b = Qr[i];
                dst[i] = make_float4(a.x + b.x, a.y + b.y, a.z + b.z, a.w + b.w);
            }
        }

        // ---- split A frags (fp16 2-term) from prefetched regs ----
        uint32 aH[4][4], aL[4][4];
#pragma unroll
        for (int kf = 0; kf < 4; kf++) {
            hsplit(ev0[2 * kf].x,     ev0[2 * kf].y,     aH[kf][0], aL[kf][0]);
            hsplit(ev1[2 * kf].x,     ev1[2 * kf].y,     aH[kf][1], aL[kf][1]);
            hsplit(ev0[2 * kf + 1].x, ev0[2 * kf + 1].y, aH[kf][2], aL[kf][2]);
            hsplit(ev1[2 * kf + 1].x, ev1[2 * kf + 1].y, aH[kf][3], aL[kf][3]);
        }

        // ---- GEMM1: acc = e @ W1[0:64]  (2-term) ----
        float acc[16][4];
#pragma unroll
        for (int nf = 0; nf < 16; nf++) {
            acc[nf][0] = 0.f; acc[nf][1] = 0.f;
            acc[nf][2] = 0.f; acc[nf][3] = 0.f;
        }
#pragma unroll
        for (int kf = 0; kf < 4; kf++) {
#pragma unroll
            for (int nf = 0; nf < 16; nf++) {
                uint2 B = sB1[(kf * 16 + nf) * 32 + lane];
                mma4(acc[nf], aH[kf], B.x, B.y);   // hi*B
                mma4(acc[nf], aL[kf], B.x, B.y);   // lo*B
            }
        }
        __syncwarp();   // staging visible before pq reads below

        // ---- prefetch next group's indices + e rows ----
        int ngrp = grp + nwarps;
        if (ngrp < ngroups) {
            int ni0 = ngrp << 4;
            int em = min(ni0 + m, E - 1);
            rowm = eidx[em];
            colm = eidx[(size_t)E + em];
            int e0i = min(ni0 + g, E - 1);
            int e1i = min(ni0 + g + 8, E - 1);
            const float* er0 = e + (size_t)e0i * D;
            const float* er1 = e + (size_t)e1i * D;
#pragma unroll
            for (int kf = 0; kf < 4; kf++) {
                ev0[2 * kf]     = *(const float2*)(er0 + kf * 16 + 2 * c);
                ev0[2 * kf + 1] = *(const float2*)(er0 + kf * 16 + 2 * c + 8);
                ev1[2 * kf]     = *(const float2*)(er1 + kf * 16 + 2 * c);
                ev1[2 * kf + 1] = *(const float2*)(er1 + kf * 16 + 2 * c + 8);
            }
        }

        // ---- +pq (smem), relu, D->A conversion (single fp16 round) ----
        // A-frag order: [0]=row g k-lo, [1]=row g+8 k-lo, [2]=row g k-hi, [3]=row g+8 k-hi
        uint32 A2[8][4];
#pragma unroll
        for (int kf = 0; kf < 8; kf++) {
            int na = 2 * kf, nb = 2 * kf + 1;
            float2 p0a = *(const float2*)(wsd + g * PQ_STRIDE + na * 8 + 2 * c);
            float2 p0b = *(const float2*)(wsd + g * PQ_STRIDE + nb * 8 + 2 * c);
            float2 p1a = *(const float2*)(wsd + (g + 8) * PQ_STRIDE + na * 8 + 2 * c);
            float2 p1b = *(const float2*)(wsd + (g + 8) * PQ_STRIDE + nb * 8 + 2 * c);
            float a0 = fmaxf(acc[na][0] + p0a.x, 0.f);
            float a1 = fmaxf(acc[na][1] + p0a.y, 0.f);
            float a2 = fmaxf(acc[nb][0] + p0b.x, 0.f);
            float a3 = fmaxf(acc[nb][1] + p0b.y, 0.f);
            float b0 = fmaxf(acc[na][2] + p1a.x, 0.f);
            float b1v = fmaxf(acc[na][3] + p1a.y, 0.f);
            float b2v = fmaxf(acc[nb][2] + p1b.x, 0.f);
            float b3 = fmaxf(acc[nb][3] + p1b.y, 0.f);
            A2[kf][0] = hround(a0, a1);    // row g,   k-lo
            A2[kf][1] = hround(b0, b1v);   // row g+8, k-lo
            A2[kf][2] = hround(a2, a3);    // row g,   k-hi
            A2[kf][3] = hround(b2v, b3);   // row g+8, k-hi
        }

        // ---- GEMM2: acc2 = b2 + relu(h1) @ W2  (1-term A; b2 folded in init) ----
        float acc2[16][4];
#pragma unroll
        for (int nf = 0; nf < 16; nf++) {
            float2 bb = *(const float2*)(sb2 + nf * 8 + 2 * c);
            acc2[nf][0] = bb.x; acc2[nf][1] = bb.y;
            acc2[nf][2] = bb.x; acc2[nf][3] = bb.y;
        }
#pragma unroll
        for (int kf = 0; kf < 8; kf++) {
#pragma unroll
            for (int nf = 0; nf < 16; nf++) {
                uint2 B = sB2[(kf * 16 + nf) * 32 + lane];
                mma4(acc2[nf], A2[kf], B.x, B.y);
            }
        }

        // ---- relu, LayerNorm stats ----
        float s0 = 0.f, ss0 = 0.f, s8 = 0.f, ss8 = 0.f;
#pragma unroll
        for (int nf = 0; nf < 16; nf++) {
            float v0 = fmaxf(acc2[nf][0], 0.f);
            float v1 = fmaxf(acc2[nf][1], 0.f);
            float v2 = fmaxf(acc2[nf][2], 0.f);
            float v3 = fmaxf(acc2[nf][3], 0.f);
            acc2[nf][0] = v0; acc2[nf][1] = v1;
            acc2[nf][2] = v2; acc2[nf][3] = v3;
            s0 += v0 + v1;  ss0 += v0 * v0 + v1 * v1;
            s8 += v2 + v3;  ss8 += v2 * v2 + v3 * v3;
        }
        s0  += __shfl_xor_sync(0xffffffffu, s0, 1);
        s0  += __shfl_xor_sync(0xffffffffu, s0, 2);
        ss0 += __shfl_xor_sync(0xffffffffu, ss0, 1);
        ss0 += __shfl_xor_sync(0xffffffffu, ss0, 2);
        s8  += __shfl_xor_sync(0xffffffffu, s8, 1);
        s8  += __shfl_xor_sync(0xffffffffu, s8, 2);
        ss8 += __shfl_xor_sync(0xffffffffu, ss8, 1);
        ss8 += __shfl_xor_sync(0xffffffffu, ss8, 2);

        float m0 = s0 * (1.0f / H);
        float r0f = rsqrtf(ss0 * (1.0f / H) - m0 * m0 + 1e-5f);
        float m8 = s8 * (1.0f / H);
        float r8f = rsqrtf(ss8 * (1.0f / H) - m8 * m8 + 1e-5f);

        int eg  = i0 + g;
        int eg8 = i0 + g + 8;
        bool w0ok = eg < E, w8ok = eg8 < E;
        float* o0 = out + (size_t)eg  * H + 2 * c;
        float* o8 = out + (size_t)eg8 * H + 2 * c;
        // lean epilogue: y = fma(v, rg, cb) with rg = r*g, cb = b - m*rg
#pragma unroll
        for (int nf = 0; nf < 16; nf++) {
            float2 gg = *(const float2*)(slg + nf * 8 + 2 * c);
            float2 be = *(const float2*)(slb + nf * 8 + 2 * c);
            if (w0ok) {
                float rgx = r0f * gg.x, rgy = r0f * gg.y;
                float cbx = fmaf(-m0, rgx, be.x);
                float cby = fmaf(-m0, rgy, be.y);
                *(float2*)(o0 + nf * 8) =
                    make_float2(fmaf(acc2[nf][0], rgx, cbx),
                                fmaf(acc2[nf][1], rgy, cby));
            }
            if (w8ok) {
                float rgx = r8f * gg.x, rgy = r8f * gg.y;
                float cbx = fmaf(-m8, rgx, be.x);
                float cby = fmaf(-m8, rgy, be.y);
                *(float2*)(o8 + nf * 8) =
                    make_float2(fmaf(acc2[nf][2], rgx, cbx),
                                fmaf(acc2[nf][3], rgy, cby));
            }
        }

        grp = ngrp;
    }
}

// ================= launch =================
extern "C" void kernel_launch(void* const* d_in, const int* in_sizes, int n_in,
                              void* d_out, int out_size) {
    const float* x     = (const float*)d_in[0];
    const float* e     = (const float*)d_in[1];
    const float* u     = (const float*)d_in[2];
    const float* W1    = (const float*)d_in[3];
    const float* b1    = (const float*)d_in[4];
    const float* W2    = (const float*)d_in[5];
    const float* b2    = (const float*)d_in[6];
    const float* ln_g  = (const float*)d_in[7];
    const float* ln_b  = (const float*)d_in[8];
    const int*   eidx  = (const int*)d_in[9];
    const int*   batch = (const int*)d_in[10];
    float*       out   = (float*)d_out;

    int N = in_sizes[0] / D;   // 100000
    int E = in_sizes[1] / D;   // 1000000

    // smem: B1 16KB + B2 32KB + consts 1.5KB + pq staging 8*8.25KB
    const int SMEM = (4 * 16 * 32 + 8 * 16 * 32) * 8 + 3 * 128 * 4
                   + EWARPS * 16 * PQ_STRIDE * 4;   // 118272 B
    cudaFuncSetAttribute(k_edge_mma, cudaFuncAttributeMaxDynamicSharedMemorySize, SMEM);

    k_preR<<<GDIM, H>>>(u, W1, b1);
    k_prePQ<<<(N + 7) / 8, 128>>>(x, W1, batch, N);
    k_edge_mma<<<152, ETHREADS, SMEM>>>(e, W1, W2, b2, ln_g, ln_b, eidx, out, E);
}